// round 6
// baseline (speedup 1.0000x reference)
#include <cuda_runtime.h>
#include <math.h>

// ============================================================================
// CKConv via FFT convolution, fused tf32 tensor-core spectrum GEMM.
//   Outf[b,o,f] = Σ_i Xf[b,i,f] · Σ_m Gf[m,f]·W3p[m, i*64+o]   (Kf never stored)
// k45: per-warp privatized B pipeline (no block barriers in the main loop),
// double-buffered cp.async, split accumulator chains.
// ============================================================================

#define LL     2048
#define NFFT   4096
#define HID    128
#define NBINS  2049   // NFFT/2 + 1

__device__ float  d_h2T[HID * LL];         // [m][l]
__device__ float  d_W3p[HID * 4096];       // [m][n'] n' = i*64+o, tf32-rounded
__device__ float2 d_tw4[NFFT];
__device__ float2 d_Gf[HID * NFFT];        // [m][f] tf32-rounded, mirrored
__device__ float2 d_Xf[128 * NFFT];        // [b*64+i][f], mirrored
__device__ float2 d_Outf[128 * NBINS];     // [b*64+o][f]

__device__ __forceinline__ float to_tf32(float x) {
    unsigned u;
    asm("cvt.rna.tf32.f32 %0, %1;" : "=r"(u) : "f"(x));
    return __uint_as_float(u);
}

// -------------------------------------------- setup: twiddles + W3 permute --
__global__ void setup_kernel(const float* __restrict__ W3) {
    int idx = blockIdx.x * blockDim.x + threadIdx.x;   // < 128*4096
    if (idx < NFFT) {
        double a = 2.0 * 3.14159265358979323846 * (double)idx / (double)NFFT;
        d_tw4[idx] = make_float2((float)cos(a), (float)(-sin(a)));
    }
    int m  = idx >> 12;
    int np = idx & 4095;
    d_W3p[idx] = to_tf32(W3[(m << 12) + ((np & 63) << 6) + (np >> 6)]);
}

// ------------------------------------------------------------ SIREN stages --
__global__ void gen_h2_kernel(const float* __restrict__ W1,
                              const float* __restrict__ W2) {
    int l = blockIdx.x;
    int j = threadIdx.x;
    __shared__ float h1[HID];
    float rel = -1.0f + 2.0f * (float)l / 2047.0f;
    h1[j] = sinf(30.0f * rel * W1[j]);
    __syncthreads();
    float acc = 0.0f;
#pragma unroll 16
    for (int m = 0; m < HID; m++)
        acc += h1[m] * W2[m * HID + j];
    d_h2T[j * LL + l] = sinf(30.0f * acc);
}

// ------------------------------------------------------- radix-4 FFT core --
__device__ __forceinline__ int rev4(int d) {
    int r = __brev(d) >> 20;
    return ((r & 0x555) << 1) | ((r & 0xAAA) >> 1);
}
__device__ __forceinline__ float2 cmul(float2 a, float2 b) {
    return make_float2(a.x * b.x - a.y * b.y, a.x * b.y + a.y * b.x);
}
__device__ __forceinline__ void fft4_core(float2* buf) {
#pragma unroll
    for (int st = 0; st < 6; st++) {
        int q = 1 << (2 * st);
        int tstep = NFFT >> (2 * st + 2);
        __syncthreads();
#pragma unroll
        for (int k = 0; k < 2; k++) {
            int bf = threadIdx.x + (k << 9);
            int j  = bf & (q - 1);
            int i0 = ((bf >> (2 * st)) << (2 * st + 2)) + j;
            float2 x0 = buf[i0];
            float2 x1 = buf[i0 + q];
            float2 x2 = buf[i0 + 2 * q];
            float2 x3 = buf[i0 + 3 * q];
            float2 u1 = cmul(x1, d_tw4[j * tstep]);
            float2 u2 = cmul(x2, d_tw4[2 * j * tstep]);
            float2 u3 = cmul(x3, d_tw4[3 * j * tstep]);
            float2 a  = make_float2(x0.x + u2.x, x0.y + u2.y);
            float2 b  = make_float2(x0.x - u2.x, x0.y - u2.y);
            float2 c  = make_float2(u1.x + u3.x, u1.y + u3.y);
            float2 dd = make_float2(u1.x - u3.x, u1.y - u3.y);
            buf[i0]         = make_float2(a.x + c.x,  a.y + c.y);
            buf[i0 + q]     = make_float2(b.x + dd.y, b.y - dd.x);
            buf[i0 + 2 * q] = make_float2(a.x - c.x,  a.y - c.y);
            buf[i0 + 3 * q] = make_float2(b.x - dd.y, b.y + dd.x);
        }
    }
    __syncthreads();
}

// ---------------------------- forward FFTs, two real rows packed per block --
__global__ void fft_gx_kernel(const float* __restrict__ x) {
    __shared__ float2 buf[NFFT];
    int blk = blockIdx.x;
    bool isg = blk < 64;
    int r0 = isg ? 2 * blk : 2 * (blk - 64);
    for (int d = threadIdx.x; d < NFFT; d += 512) {
        int src = rev4(d);
        float va = 0.0f, vb = 0.0f;
        if (src < LL) {
            if (isg) {
                va = d_h2T[r0 * LL + (LL - 1 - src)];
                vb = d_h2T[(r0 + 1) * LL + (LL - 1 - src)];
            } else {
                va = x[r0 * LL + src];
                vb = x[(r0 + 1) * LL + src];
            }
        }
        buf[d] = make_float2(va, vb);
    }
    fft4_core(buf);
    for (int f = threadIdx.x; f <= 2048; f += 512) {
        float2 Zf = buf[f];
        float2 Zc = buf[(NFFT - f) & (NFFT - 1)];
        float2 A = make_float2((Zf.x + Zc.x) * 0.5f, (Zf.y - Zc.y) * 0.5f);
        float2 B = make_float2((Zf.y + Zc.y) * 0.5f, (Zc.x - Zf.x) * 0.5f);
        if (isg) {
            A = make_float2(to_tf32(A.x), to_tf32(A.y));
            B = make_float2(to_tf32(B.x), to_tf32(B.y));
            d_Gf[r0 * NFFT + f]       = A;
            d_Gf[(r0 + 1) * NFFT + f] = B;
            if (f > 0 && f < 2048) {
                d_Gf[r0 * NFFT + NFFT - f]       = make_float2(A.x, -A.y);
                d_Gf[(r0 + 1) * NFFT + NFFT - f] = make_float2(B.x, -B.y);
            }
        } else {
            d_Xf[r0 * NFFT + f]       = A;
            d_Xf[(r0 + 1) * NFFT + f] = B;
            if (f > 0 && f < 2048) {
                d_Xf[r0 * NFFT + NFFT - f]       = make_float2(A.x, -A.y);
                d_Xf[(r0 + 1) * NFFT + NFFT - f] = make_float2(B.x, -B.y);
            }
        }
    }
}

// ----------------------- k45: fused kernel-spectrum GEMM + per-bin mixing --
#define MMA_TF32(C, A, B0, B1)                                              \
    asm volatile("mma.sync.aligned.m16n8k8.row.col.f32.tf32.tf32.f32 "      \
        "{%0,%1,%2,%3}, {%4,%5,%6,%7}, {%8,%9}, {%0,%1,%2,%3};"             \
        : "+f"(C[0]), "+f"(C[1]), "+f"(C[2]), "+f"(C[3])                    \
        : "r"(A[0]), "r"(A[1]), "r"(A[2]), "r"(A[3]), "r"(B0), "r"(B1))

#define CP16(dst_u32, src_ptr)                                              \
    asm volatile("cp.async.cg.shared.global [%0], [%1], 16;"                \
                 :: "r"(dst_u32), "l"(src_ptr))

// smem: Xs [128][16] float2 (16 KB) + per-warp B slices 8 warps x 2 bufs x
// (128 k x 8 o) floats (64 KB) = 80 KB dynamic.
#define XS_FLOATS   (128 * 16 * 2)
#define WSLICE      (HID * 8)                         // 1024 floats
#define K45_SMEM    ((XS_FLOATS + 8 * 2 * WSLICE) * 4)

__global__ void __launch_bounds__(256) k45_kernel() {
    extern __shared__ float smem[];
    float2* Xs = (float2*)smem;

    const int f0   = blockIdx.x * 16;           // grid 129
    const int tid  = threadIdx.x;
    const int lane = tid & 31;
    const int warp = tid >> 5;
    const int g    = lane >> 2;
    const int tg   = lane & 3;
    const int obase = warp * 8;

    float* Bw = smem + XS_FLOATS + warp * (2 * WSLICE);   // this warp's slices
    unsigned bw_base = (unsigned)__cvta_generic_to_shared(Bw);

    // per-warp slice load: W3p[0:128, i*64+obase : +8] -> Bw[buf]
    // 256 16B-chunks (128 rows x 2), 8 per lane.
#define LOAD_SLICE(i_, buf_)                                                \
    {                                                                       \
        const float* srcb = d_W3p + (i_) * 64 + obase;                      \
        unsigned dstb = bw_base + (buf_) * (WSLICE * 4);                    \
        _Pragma("unroll")                                                   \
        for (int j = 0; j < 8; j++) {                                       \
            int c = lane + (j << 5);            /* 0..255 */                \
            int row = c >> 1, half = c & 1;                                 \
            CP16(dstb + (row * 8 + half * 4) * 4,                           \
                 srcb + row * 4096 + half * 4);                             \
        }                                                                   \
    }

    LOAD_SLICE(0, 0);
    asm volatile("cp.async.commit_group;");

    for (int idx = tid; idx < 128 * 16; idx += 256) {
        int row = idx >> 4, ff = idx & 15;
        Xs[idx] = d_Xf[row * NFFT + f0 + ff];
    }

    // Hoist A fragments (Gf, complex) for the whole f-tile.
    unsigned aR[16][4], aI[16][4];
#pragma unroll
    for (int k0 = 0; k0 < 16; k0++) {
        int kk = k0 * 8;
        float2 v0 = d_Gf[(kk + tg)     * NFFT + f0 + g];
        float2 v1 = d_Gf[(kk + tg)     * NFFT + f0 + g + 8];
        float2 v2 = d_Gf[(kk + tg + 4) * NFFT + f0 + g];
        float2 v3 = d_Gf[(kk + tg + 4) * NFFT + f0 + g + 8];
        aR[k0][0] = __float_as_uint(v0.x); aI[k0][0] = __float_as_uint(v0.y);
        aR[k0][1] = __float_as_uint(v1.x); aI[k0][1] = __float_as_uint(v1.y);
        aR[k0][2] = __float_as_uint(v2.x); aI[k0][2] = __float_as_uint(v2.y);
        aR[k0][3] = __float_as_uint(v3.x); aI[k0][3] = __float_as_uint(v3.y);
    }

    float oR[2][2][2] = {}, oI[2][2][2] = {};

    __syncthreads();     // Xs visible to all warps; last block-wide barrier.

    for (int i = 0; i < 64; i++) {
        if (i < 63) {
            LOAD_SLICE(i + 1, (i + 1) & 1);
            asm volatile("cp.async.commit_group;");
            asm volatile("cp.async.wait_group 1;");   // slice i done; i+1 in flight
        } else {
            asm volatile("cp.async.wait_group 0;");
        }
        __syncwarp();

        // split accumulators: even/odd k chains (depth 8 each)
        float cR0[4] = {0,0,0,0}, cR1[4] = {0,0,0,0};
        float cI0[4] = {0,0,0,0}, cI1[4] = {0,0,0,0};
        const float* Bp = Bw + (i & 1) * WSLICE + g;
#pragma unroll
        for (int k0 = 0; k0 < 16; k0 += 2) {
            unsigned b0 = __float_as_uint(Bp[(k0 * 8 + tg) * 8]);
            unsigned b1 = __float_as_uint(Bp[(k0 * 8 + tg + 4) * 8]);
            unsigned b2 = __float_as_uint(Bp[((k0 + 1) * 8 + tg) * 8]);
            unsigned b3 = __float_as_uint(Bp[((k0 + 1) * 8 + tg + 4) * 8]);
            MMA_TF32(cR0, aR[k0], b0, b1);
            MMA_TF32(cI0, aI[k0], b0, b1);
            MMA_TF32(cR1, aR[k0 + 1], b2, b3);
            MMA_TF32(cI1, aI[k0 + 1], b2, b3);
        }
        // epilogue: Out[b,o,f] += Xf[b,i,f] * Kf
#pragma unroll
        for (int rr = 0; rr < 2; rr++) {
            int flocal = g + rr * 8;
#pragma unroll
            for (int b = 0; b < 2; b++) {
                float2 xv = Xs[(b * 64 + i) * 16 + flocal];
#pragma unroll
                for (int cc = 0; cc < 2; cc++) {
                    float kr = cR0[rr * 2 + cc] + cR1[rr * 2 + cc];
                    float ki = cI0[rr * 2 + cc] + cI1[rr * 2 + cc];
                    oR[b][rr][cc] += xv.x * kr - xv.y * ki;
                    oI[b][rr][cc] += xv.x * ki + xv.y * kr;
                }
            }
        }
    }

#pragma unroll
    for (int rr = 0; rr < 2; rr++) {
        int f = f0 + g + rr * 8;
        if (f < NBINS) {
#pragma unroll
            for (int b = 0; b < 2; b++)
#pragma unroll
                for (int cc = 0; cc < 2; cc++) {
                    int o = obase + tg * 2 + cc;
                    d_Outf[(b * 64 + o) * NBINS + f] =
                        make_float2(oR[b][rr][cc], oI[b][rr][cc]);
                }
        }
    }
}

// ------------------- inverse FFT: two real output rows packed per block ----
__global__ void fft_inv_kernel(float* __restrict__ out) {
    __shared__ float2 buf[NFFT];
    int t0 = 2 * blockIdx.x;
    const float2* O0 = d_Outf + (size_t)t0 * NBINS;
    const float2* O1 = d_Outf + (size_t)(t0 + 1) * NBINS;
    for (int d = threadIdx.x; d < NFFT; d += 512) {
        int src = rev4(d);
        float2 v;
        if (src <= 2048) {
            float2 a = O0[src], b = O1[src];
            v = make_float2(a.x - b.y, -a.y - b.x);
        } else {
            int s = NFFT - src;
            float2 a = O0[s], b = O1[s];
            v = make_float2(a.x + b.y, a.y - b.x);
        }
        buf[d] = v;
    }
    fft4_core(buf);
    const float inv = 1.0f / (float)NFFT;
    for (int n = threadIdx.x; n < LL; n += 512) {
        out[t0 * LL + n]       =  buf[n].x * inv;
        out[(t0 + 1) * LL + n] = -buf[n].y * inv;
    }
}

// ============================================================================
extern "C" void kernel_launch(void* const* d_in, const int* in_sizes, int n_in,
                              void* d_out, int out_size) {
    (void)in_sizes; (void)n_in; (void)out_size;
    const float* x  = (const float*)d_in[0];
    const float* W1 = (const float*)d_in[1];
    const float* W2 = (const float*)d_in[2];
    const float* W3 = (const float*)d_in[3];
    float* out = (float*)d_out;

    cudaFuncSetAttribute(k45_kernel,
                         cudaFuncAttributeMaxDynamicSharedMemorySize, K45_SMEM);

    setup_kernel<<<2048, 256>>>(W3);
    gen_h2_kernel<<<2048, 128>>>(W1, W2);
    fft_gx_kernel<<<128, 512>>>(x);
    k45_kernel<<<129, 256, K45_SMEM>>>();
    fft_inv_kernel<<<64, 512>>>(out);
}

// round 7
// speedup vs baseline: 1.1345x; 1.1345x over previous
#include <cuda_runtime.h>
#include <math.h>

// ============================================================================
// CKConv via FFT convolution, fused tf32 tensor-core spectrum GEMM.
//   Outf[b,o,f] = Σ_i Xf[b,i,f] · Σ_m Gf[m,f]·W3p[m, i*64+o]   (Kf never stored)
// k45 split over k-halves across blocks (grid 129x2) -> 2 CTAs/SM, partial
// outputs summed inside the inverse FFT.
// ============================================================================

#define LL     2048
#define NFFT   4096
#define HID    128
#define NBINS  2049   // NFFT/2 + 1

__device__ float  d_h2T[HID * LL];         // [m][l]
__device__ float  d_W3p[HID * 4096];       // [m][n'] n' = i*64+o, tf32-rounded
__device__ float2 d_tw4[NFFT];
__device__ float2 d_Gf[HID * NFFT];        // [m][f] tf32-rounded, mirrored
__device__ float2 d_Xf[128 * NFFT];        // [b*64+i][f], mirrored
__device__ float2 d_OutfP[2][128 * NBINS]; // per-k-half partials

__device__ __forceinline__ float to_tf32(float x) {
    unsigned u;
    asm("cvt.rna.tf32.f32 %0, %1;" : "=r"(u) : "f"(x));
    return __uint_as_float(u);
}

// -------------------------------------------- setup: twiddles + W3 permute --
__global__ void setup_kernel(const float* __restrict__ W3) {
    int idx = blockIdx.x * blockDim.x + threadIdx.x;   // < 128*4096
    if (idx < NFFT) {
        double a = 2.0 * 3.14159265358979323846 * (double)idx / (double)NFFT;
        d_tw4[idx] = make_float2((float)cos(a), (float)(-sin(a)));
    }
    int m  = idx >> 12;
    int np = idx & 4095;
    d_W3p[idx] = to_tf32(W3[(m << 12) + ((np & 63) << 6) + (np >> 6)]);
}

// ------------------------------------------------------------ SIREN stages --
__global__ void gen_h2_kernel(const float* __restrict__ W1,
                              const float* __restrict__ W2) {
    int l = blockIdx.x;
    int j = threadIdx.x;
    __shared__ float h1[HID];
    float rel = -1.0f + 2.0f * (float)l / 2047.0f;
    h1[j] = sinf(30.0f * rel * W1[j]);
    __syncthreads();
    float acc = 0.0f;
#pragma unroll 16
    for (int m = 0; m < HID; m++)
        acc += h1[m] * W2[m * HID + j];
    d_h2T[j * LL + l] = sinf(30.0f * acc);
}

// ------------------------------------------------------- radix-4 FFT core --
__device__ __forceinline__ int rev4(int d) {
    int r = __brev(d) >> 20;
    return ((r & 0x555) << 1) | ((r & 0xAAA) >> 1);
}
__device__ __forceinline__ float2 cmul(float2 a, float2 b) {
    return make_float2(a.x * b.x - a.y * b.y, a.x * b.y + a.y * b.x);
}
__device__ __forceinline__ void fft4_core(float2* buf) {
#pragma unroll
    for (int st = 0; st < 6; st++) {
        int q = 1 << (2 * st);
        int tstep = NFFT >> (2 * st + 2);
        __syncthreads();
#pragma unroll
        for (int k = 0; k < 2; k++) {
            int bf = threadIdx.x + (k << 9);
            int j  = bf & (q - 1);
            int i0 = ((bf >> (2 * st)) << (2 * st + 2)) + j;
            float2 x0 = buf[i0];
            float2 x1 = buf[i0 + q];
            float2 x2 = buf[i0 + 2 * q];
            float2 x3 = buf[i0 + 3 * q];
            float2 u1 = cmul(x1, d_tw4[j * tstep]);
            float2 u2 = cmul(x2, d_tw4[2 * j * tstep]);
            float2 u3 = cmul(x3, d_tw4[3 * j * tstep]);
            float2 a  = make_float2(x0.x + u2.x, x0.y + u2.y);
            float2 b  = make_float2(x0.x - u2.x, x0.y - u2.y);
            float2 c  = make_float2(u1.x + u3.x, u1.y + u3.y);
            float2 dd = make_float2(u1.x - u3.x, u1.y - u3.y);
            buf[i0]         = make_float2(a.x + c.x,  a.y + c.y);
            buf[i0 + q]     = make_float2(b.x + dd.y, b.y - dd.x);
            buf[i0 + 2 * q] = make_float2(a.x - c.x,  a.y - c.y);
            buf[i0 + 3 * q] = make_float2(b.x - dd.y, b.y + dd.x);
        }
    }
    __syncthreads();
}

// ---------------------------- forward FFTs, two real rows packed per block --
__global__ void fft_gx_kernel(const float* __restrict__ x) {
    __shared__ float2 buf[NFFT];
    int blk = blockIdx.x;
    bool isg = blk < 64;
    int r0 = isg ? 2 * blk : 2 * (blk - 64);
    for (int d = threadIdx.x; d < NFFT; d += 512) {
        int src = rev4(d);
        float va = 0.0f, vb = 0.0f;
        if (src < LL) {
            if (isg) {
                va = d_h2T[r0 * LL + (LL - 1 - src)];
                vb = d_h2T[(r0 + 1) * LL + (LL - 1 - src)];
            } else {
                va = x[r0 * LL + src];
                vb = x[(r0 + 1) * LL + src];
            }
        }
        buf[d] = make_float2(va, vb);
    }
    fft4_core(buf);
    for (int f = threadIdx.x; f <= 2048; f += 512) {
        float2 Zf = buf[f];
        float2 Zc = buf[(NFFT - f) & (NFFT - 1)];
        float2 A = make_float2((Zf.x + Zc.x) * 0.5f, (Zf.y - Zc.y) * 0.5f);
        float2 B = make_float2((Zf.y + Zc.y) * 0.5f, (Zc.x - Zf.x) * 0.5f);
        if (isg) {
            A = make_float2(to_tf32(A.x), to_tf32(A.y));
            B = make_float2(to_tf32(B.x), to_tf32(B.y));
            d_Gf[r0 * NFFT + f]       = A;
            d_Gf[(r0 + 1) * NFFT + f] = B;
            if (f > 0 && f < 2048) {
                d_Gf[r0 * NFFT + NFFT - f]       = make_float2(A.x, -A.y);
                d_Gf[(r0 + 1) * NFFT + NFFT - f] = make_float2(B.x, -B.y);
            }
        } else {
            d_Xf[r0 * NFFT + f]       = A;
            d_Xf[(r0 + 1) * NFFT + f] = B;
            if (f > 0 && f < 2048) {
                d_Xf[r0 * NFFT + NFFT - f]       = make_float2(A.x, -A.y);
                d_Xf[(r0 + 1) * NFFT + NFFT - f] = make_float2(B.x, -B.y);
            }
        }
    }
}

// ----------------------- k45: fused kernel-spectrum GEMM + per-bin mixing --
#define MMA_TF32(C, A, B0, B1)                                              \
    asm volatile("mma.sync.aligned.m16n8k8.row.col.f32.tf32.tf32.f32 "      \
        "{%0,%1,%2,%3}, {%4,%5,%6,%7}, {%8,%9}, {%0,%1,%2,%3};"             \
        : "+f"(C[0]), "+f"(C[1]), "+f"(C[2]), "+f"(C[3])                    \
        : "r"(A[0]), "r"(A[1]), "r"(A[2]), "r"(A[3]), "r"(B0), "r"(B1))

#define CP16(dst_u32, src_ptr)                                              \
    asm volatile("cp.async.cg.shared.global [%0], [%1], 16;"                \
                 :: "r"(dst_u32), "l"(src_ptr))

// smem: Xs [128][16] float2 (16 KB) + per-warp B slices 8 warps x 2 bufs x
// (64 k x 8 o) floats (32 KB) = 48 KB dynamic. 2 CTAs/SM -> 96 KB.
#define XS_FLOATS   (128 * 16 * 2)
#define WSLICE      (64 * 8)                          // 512 floats (k-half)
#define K45_SMEM    ((XS_FLOATS + 8 * 2 * WSLICE) * 4)

__global__ void __launch_bounds__(256, 2) k45_kernel() {
    extern __shared__ float smem[];
    float2* Xs = (float2*)smem;

    const int f0   = blockIdx.x * 16;           // 129 f-tiles
    const int kh   = blockIdx.y;                // k-half: 0 or 1
    const int kofs = kh * 64;
    const int tid  = threadIdx.x;
    const int lane = tid & 31;
    const int warp = tid >> 5;
    const int g    = lane >> 2;
    const int tg   = lane & 3;
    const int obase = warp * 8;

    float* Bw = smem + XS_FLOATS + warp * (2 * WSLICE);
    unsigned bw_base = (unsigned)__cvta_generic_to_shared(Bw);

    // per-warp slice: W3p[kofs:kofs+64, i*64+obase : +8] -> Bw[buf]
    // 128 16B-chunks (64 rows x 2), 4 per lane.
#define LOAD_SLICE(i_, buf_)                                                \
    {                                                                       \
        const float* srcb = d_W3p + (size_t)kofs * 4096 + (i_) * 64 + obase;\
        unsigned dstb = bw_base + (buf_) * (WSLICE * 4);                    \
        _Pragma("unroll")                                                   \
        for (int j = 0; j < 4; j++) {                                       \
            int c = lane + (j << 5);            /* 0..127 */                \
            int row = c >> 1, half = c & 1;                                 \
            CP16(dstb + (row * 8 + half * 4) * 4,                           \
                 srcb + row * 4096 + half * 4);                             \
        }                                                                   \
    }

    LOAD_SLICE(0, 0);
    asm volatile("cp.async.commit_group;");

    for (int idx = tid; idx < 128 * 16; idx += 256) {
        int row = idx >> 4, ff = idx & 15;
        Xs[idx] = d_Xf[row * NFFT + f0 + ff];
    }

    // Hoist A fragments (Gf, complex) for this k-half: 8 steps, 64 regs.
    unsigned aR[8][4], aI[8][4];
#pragma unroll
    for (int k0 = 0; k0 < 8; k0++) {
        int kk = kofs + k0 * 8;
        float2 v0 = d_Gf[(kk + tg)     * NFFT + f0 + g];
        float2 v1 = d_Gf[(kk + tg)     * NFFT + f0 + g + 8];
        float2 v2 = d_Gf[(kk + tg + 4) * NFFT + f0 + g];
        float2 v3 = d_Gf[(kk + tg + 4) * NFFT + f0 + g + 8];
        aR[k0][0] = __float_as_uint(v0.x); aI[k0][0] = __float_as_uint(v0.y);
        aR[k0][1] = __float_as_uint(v1.x); aI[k0][1] = __float_as_uint(v1.y);
        aR[k0][2] = __float_as_uint(v2.x); aI[k0][2] = __float_as_uint(v2.y);
        aR[k0][3] = __float_as_uint(v3.x); aI[k0][3] = __float_as_uint(v3.y);
    }

    float oR[2][2][2] = {}, oI[2][2][2] = {};

    __syncthreads();     // Xs visible; last block-wide barrier.

    for (int i = 0; i < 64; i++) {
        if (i < 63) {
            LOAD_SLICE(i + 1, (i + 1) & 1);
            asm volatile("cp.async.commit_group;");
            asm volatile("cp.async.wait_group 1;");
        } else {
            asm volatile("cp.async.wait_group 0;");
        }
        __syncwarp();

        float cR0[4] = {0,0,0,0}, cR1[4] = {0,0,0,0};
        float cI0[4] = {0,0,0,0}, cI1[4] = {0,0,0,0};
        const float* Bp = Bw + (i & 1) * WSLICE + g;
#pragma unroll
        for (int k0 = 0; k0 < 8; k0 += 2) {
            unsigned b0 = __float_as_uint(Bp[(k0 * 8 + tg) * 8]);
            unsigned b1 = __float_as_uint(Bp[(k0 * 8 + tg + 4) * 8]);
            unsigned b2 = __float_as_uint(Bp[((k0 + 1) * 8 + tg) * 8]);
            unsigned b3 = __float_as_uint(Bp[((k0 + 1) * 8 + tg + 4) * 8]);
            MMA_TF32(cR0, aR[k0], b0, b1);
            MMA_TF32(cI0, aI[k0], b0, b1);
            MMA_TF32(cR1, aR[k0 + 1], b2, b3);
            MMA_TF32(cI1, aI[k0 + 1], b2, b3);
        }
#pragma unroll
        for (int rr = 0; rr < 2; rr++) {
            int flocal = g + rr * 8;
#pragma unroll
            for (int b = 0; b < 2; b++) {
                float2 xv = Xs[(b * 64 + i) * 16 + flocal];
#pragma unroll
                for (int cc = 0; cc < 2; cc++) {
                    float kr = cR0[rr * 2 + cc] + cR1[rr * 2 + cc];
                    float ki = cI0[rr * 2 + cc] + cI1[rr * 2 + cc];
                    oR[b][rr][cc] += xv.x * kr - xv.y * ki;
                    oI[b][rr][cc] += xv.x * ki + xv.y * kr;
                }
            }
        }
    }

#pragma unroll
    for (int rr = 0; rr < 2; rr++) {
        int f = f0 + g + rr * 8;
        if (f < NBINS) {
#pragma unroll
            for (int b = 0; b < 2; b++)
#pragma unroll
                for (int cc = 0; cc < 2; cc++) {
                    int o = obase + tg * 2 + cc;
                    d_OutfP[kh][(b * 64 + o) * NBINS + f] =
                        make_float2(oR[b][rr][cc], oI[b][rr][cc]);
                }
        }
    }
}

// ------------------- inverse FFT: sums k-half partials, 2 rows per block ----
__global__ void fft_inv_kernel(float* __restrict__ out) {
    __shared__ float2 buf[NFFT];
    int t0 = 2 * blockIdx.x;
    const float2* P00 = d_OutfP[0] + (size_t)t0 * NBINS;
    const float2* P01 = d_OutfP[1] + (size_t)t0 * NBINS;
    const float2* P10 = d_OutfP[0] + (size_t)(t0 + 1) * NBINS;
    const float2* P11 = d_OutfP[1] + (size_t)(t0 + 1) * NBINS;
    for (int d = threadIdx.x; d < NFFT; d += 512) {
        int src = rev4(d);
        int s = (src <= 2048) ? src : (NFFT - src);
        float2 a = make_float2(P00[s].x + P01[s].x, P00[s].y + P01[s].y);
        float2 b = make_float2(P10[s].x + P11[s].x, P10[s].y + P11[s].y);
        float2 v;
        if (src <= 2048) v = make_float2(a.x - b.y, -a.y - b.x);
        else             v = make_float2(a.x + b.y,  a.y - b.x);
        buf[d] = v;
    }
    fft4_core(buf);
    const float inv = 1.0f / (float)NFFT;
    for (int n = threadIdx.x; n < LL; n += 512) {
        out[t0 * LL + n]       =  buf[n].x * inv;
        out[(t0 + 1) * LL + n] = -buf[n].y * inv;
    }
}

// ============================================================================
extern "C" void kernel_launch(void* const* d_in, const int* in_sizes, int n_in,
                              void* d_out, int out_size) {
    (void)in_sizes; (void)n_in; (void)out_size;
    const float* x  = (const float*)d_in[0];
    const float* W1 = (const float*)d_in[1];
    const float* W2 = (const float*)d_in[2];
    const float* W3 = (const float*)d_in[3];
    float* out = (float*)d_out;

    cudaFuncSetAttribute(k45_kernel,
                         cudaFuncAttributeMaxDynamicSharedMemorySize, K45_SMEM);

    setup_kernel<<<2048, 256>>>(W3);
    gen_h2_kernel<<<2048, 128>>>(W1, W2);
    fft_gx_kernel<<<128, 512>>>(x);
    k45_kernel<<<dim3(129, 2), 256, K45_SMEM>>>();
    fft_inv_kernel<<<64, 512>>>(out);
}

// round 8
// speedup vs baseline: 1.3047x; 1.1500x over previous
#include <cuda_runtime.h>
#include <math.h>

// ============================================================================
// CKConv via FFT convolution, fused tf32 tensor-core spectrum GEMM.
//   Outf[b,o,f] = Σ_i Xf[b,i,f] · Σ_m Gf[m,f]·W3p[m, i*64+o]   (Kf never stored)
// k45: grid 129x2 (k-halves), 4-deep per-warp cp.async pipeline, W3 stored in
// fragment-ready order (LDS.64 B-operand loads).
// ============================================================================

#define LL     2048
#define NFFT   4096
#define HID    128
#define NBINS  2049   // NFFT/2 + 1

__device__ float  d_h2T[HID * LL];         // [m][l]
__device__ float2 d_W3f[64 * 8 * 16 * 32]; // [i][warp][kchunk][lane] frag pairs
__device__ float2 d_tw4[NFFT];
__device__ float2 d_Gf[HID * NFFT];        // [m][f] tf32-rounded, mirrored
__device__ float2 d_Xf[128 * NFFT];        // [b*64+i][f], mirrored
__device__ float2 d_OutfP[2][128 * NBINS]; // per-k-half partials

__device__ __forceinline__ float to_tf32(float x) {
    unsigned u;
    asm("cvt.rna.tf32.f32 %0, %1;" : "=r"(u) : "f"(x));
    return __uint_as_float(u);
}

// ---------------- setup: twiddles + W3 fragment-order repack (tf32) --------
// d_W3f[((i*8+w)*16+kc)*32 + lane] = ( W3[(kc*8+tg)*4096 + o*64 + i],
//                                      W3[(kc*8+tg+4)*4096 + o*64 + i] )
// with o = w*8 + (lane>>2), tg = lane&3.
__global__ void setup_kernel(const float* __restrict__ W3) {
    int idx = blockIdx.x * blockDim.x + threadIdx.x;   // < 262144
    if (idx < NFFT) {
        double a = 2.0 * 3.14159265358979323846 * (double)idx / (double)NFFT;
        d_tw4[idx] = make_float2((float)cos(a), (float)(-sin(a)));
    }
    int lane = idx & 31;
    int kc   = (idx >> 5) & 15;
    int w    = (idx >> 9) & 7;
    int i    = idx >> 12;
    int tg = lane & 3, g = lane >> 2;
    int col = (w * 8 + g) * 64 + i;
    int m0  = kc * 8 + tg;
    d_W3f[idx] = make_float2(to_tf32(W3[m0 * 4096 + col]),
                             to_tf32(W3[(m0 + 4) * 4096 + col]));
}

// ------------------------------------------------------------ SIREN stages --
__global__ void gen_h2_kernel(const float* __restrict__ W1,
                              const float* __restrict__ W2) {
    int l = blockIdx.x;
    int j = threadIdx.x;
    __shared__ float h1[HID];
    float rel = -1.0f + 2.0f * (float)l / 2047.0f;
    h1[j] = sinf(30.0f * rel * W1[j]);
    __syncthreads();
    float acc = 0.0f;
#pragma unroll 16
    for (int m = 0; m < HID; m++)
        acc += h1[m] * W2[m * HID + j];
    d_h2T[j * LL + l] = sinf(30.0f * acc);
}

// ------------------------------------------------------- radix-4 FFT core --
__device__ __forceinline__ int rev4(int d) {
    int r = __brev(d) >> 20;
    return ((r & 0x555) << 1) | ((r & 0xAAA) >> 1);
}
__device__ __forceinline__ float2 cmul(float2 a, float2 b) {
    return make_float2(a.x * b.x - a.y * b.y, a.x * b.y + a.y * b.x);
}
__device__ __forceinline__ void fft4_core(float2* buf) {
#pragma unroll
    for (int st = 0; st < 6; st++) {
        int q = 1 << (2 * st);
        int tstep = NFFT >> (2 * st + 2);
        __syncthreads();
#pragma unroll
        for (int k = 0; k < 2; k++) {
            int bf = threadIdx.x + (k << 9);
            int j  = bf & (q - 1);
            int i0 = ((bf >> (2 * st)) << (2 * st + 2)) + j;
            float2 x0 = buf[i0];
            float2 x1 = buf[i0 + q];
            float2 x2 = buf[i0 + 2 * q];
            float2 x3 = buf[i0 + 3 * q];
            float2 u1 = cmul(x1, d_tw4[j * tstep]);
            float2 u2 = cmul(x2, d_tw4[2 * j * tstep]);
            float2 u3 = cmul(x3, d_tw4[3 * j * tstep]);
            float2 a  = make_float2(x0.x + u2.x, x0.y + u2.y);
            float2 b  = make_float2(x0.x - u2.x, x0.y - u2.y);
            float2 c  = make_float2(u1.x + u3.x, u1.y + u3.y);
            float2 dd = make_float2(u1.x - u3.x, u1.y - u3.y);
            buf[i0]         = make_float2(a.x + c.x,  a.y + c.y);
            buf[i0 + q]     = make_float2(b.x + dd.y, b.y - dd.x);
            buf[i0 + 2 * q] = make_float2(a.x - c.x,  a.y - c.y);
            buf[i0 + 3 * q] = make_float2(b.x - dd.y, b.y + dd.x);
        }
    }
    __syncthreads();
}

// ---------------------------- forward FFTs, two real rows packed per block --
__global__ void fft_gx_kernel(const float* __restrict__ x) {
    __shared__ float2 buf[NFFT];
    int blk = blockIdx.x;
    bool isg = blk < 64;
    int r0 = isg ? 2 * blk : 2 * (blk - 64);
    for (int d = threadIdx.x; d < NFFT; d += 512) {
        int src = rev4(d);
        float va = 0.0f, vb = 0.0f;
        if (src < LL) {
            if (isg) {
                va = d_h2T[r0 * LL + (LL - 1 - src)];
                vb = d_h2T[(r0 + 1) * LL + (LL - 1 - src)];
            } else {
                va = x[r0 * LL + src];
                vb = x[(r0 + 1) * LL + src];
            }
        }
        buf[d] = make_float2(va, vb);
    }
    fft4_core(buf);
    for (int f = threadIdx.x; f <= 2048; f += 512) {
        float2 Zf = buf[f];
        float2 Zc = buf[(NFFT - f) & (NFFT - 1)];
        float2 A = make_float2((Zf.x + Zc.x) * 0.5f, (Zf.y - Zc.y) * 0.5f);
        float2 B = make_float2((Zf.y + Zc.y) * 0.5f, (Zc.x - Zf.x) * 0.5f);
        if (isg) {
            A = make_float2(to_tf32(A.x), to_tf32(A.y));
            B = make_float2(to_tf32(B.x), to_tf32(B.y));
            d_Gf[r0 * NFFT + f]       = A;
            d_Gf[(r0 + 1) * NFFT + f] = B;
            if (f > 0 && f < 2048) {
                d_Gf[r0 * NFFT + NFFT - f]       = make_float2(A.x, -A.y);
                d_Gf[(r0 + 1) * NFFT + NFFT - f] = make_float2(B.x, -B.y);
            }
        } else {
            d_Xf[r0 * NFFT + f]       = A;
            d_Xf[(r0 + 1) * NFFT + f] = B;
            if (f > 0 && f < 2048) {
                d_Xf[r0 * NFFT + NFFT - f]       = make_float2(A.x, -A.y);
                d_Xf[(r0 + 1) * NFFT + NFFT - f] = make_float2(B.x, -B.y);
            }
        }
    }
}

// ----------------------- k45: fused kernel-spectrum GEMM + per-bin mixing --
#define MMA_TF32(C, A, B0, B1)                                              \
    asm volatile("mma.sync.aligned.m16n8k8.row.col.f32.tf32.tf32.f32 "      \
        "{%0,%1,%2,%3}, {%4,%5,%6,%7}, {%8,%9}, {%0,%1,%2,%3};"             \
        : "+f"(C[0]), "+f"(C[1]), "+f"(C[2]), "+f"(C[3])                    \
        : "r"(A[0]), "r"(A[1]), "r"(A[2]), "r"(A[3]), "r"(B0), "r"(B1))

#define CP16(dst_u32, src_ptr)                                              \
    asm volatile("cp.async.cg.shared.global [%0], [%1], 16;"                \
                 :: "r"(dst_u32), "l"(src_ptr))

// smem: Xs [128][16] float2 (16 KB) + 8 warps x 4 bufs x 256 float2 (64 KB)
#define XS_FLOATS   (128 * 16 * 2)
#define SLICE_F2    256                         // float2 per buffer (2 KB)
#define K45_SMEM    (XS_FLOATS * 4 + 8 * 4 * SLICE_F2 * 8)

__global__ void __launch_bounds__(256, 2) k45_kernel() {
    extern __shared__ float smem[];
    float2* Xs = (float2*)smem;

    const int f0   = blockIdx.x * 16;           // 129 f-tiles
    const int kh   = blockIdx.y;                // k-half
    const int kofs = kh * 64;
    const int tid  = threadIdx.x;
    const int lane = tid & 31;
    const int warp = tid >> 5;
    const int g    = lane >> 2;
    const int tg   = lane & 3;
    const int obase = warp * 8;

    float2* Bw = (float2*)smem + XS_FLOATS / 2 + warp * (4 * SLICE_F2);
    unsigned bw_base = (unsigned)__cvta_generic_to_shared(Bw);

    // per-warp fragment slice: d_W3f[((i*8+warp)*16 + kh*8) ... +8*32] float2
#define LOAD_SLICE(i_, buf_)                                                \
    {                                                                       \
        const float2* srcb = d_W3f + (((i_) * 8 + warp) * 16 + kh * 8) * 32;\
        unsigned dstb = bw_base + (buf_) * (SLICE_F2 * 8);                  \
        _Pragma("unroll")                                                   \
        for (int j = 0; j < 4; j++) {                                       \
            int c = lane + (j << 5);            /* 16B chunk id, 0..127 */  \
            CP16(dstb + c * 16, srcb + c * 2);                              \
        }                                                                   \
    }

    LOAD_SLICE(0, 0); asm volatile("cp.async.commit_group;");
    LOAD_SLICE(1, 1); asm volatile("cp.async.commit_group;");
    LOAD_SLICE(2, 2); asm volatile("cp.async.commit_group;");

    for (int idx = tid; idx < 128 * 16; idx += 256) {
        int row = idx >> 4, ff = idx & 15;
        Xs[idx] = d_Xf[row * NFFT + f0 + ff];
    }

    // Hoist A fragments (Gf, complex) for this k-half: 8 steps.
    unsigned aR[8][4], aI[8][4];
#pragma unroll
    for (int k0 = 0; k0 < 8; k0++) {
        int kk = kofs + k0 * 8;
        float2 v0 = d_Gf[(kk + tg)     * NFFT + f0 + g];
        float2 v1 = d_Gf[(kk + tg)     * NFFT + f0 + g + 8];
        float2 v2 = d_Gf[(kk + tg + 4) * NFFT + f0 + g];
        float2 v3 = d_Gf[(kk + tg + 4) * NFFT + f0 + g + 8];
        aR[k0][0] = __float_as_uint(v0.x); aI[k0][0] = __float_as_uint(v0.y);
        aR[k0][1] = __float_as_uint(v1.x); aI[k0][1] = __float_as_uint(v1.y);
        aR[k0][2] = __float_as_uint(v2.x); aI[k0][2] = __float_as_uint(v2.y);
        aR[k0][3] = __float_as_uint(v3.x); aI[k0][3] = __float_as_uint(v3.y);
    }

    float oR[2][2][2] = {}, oI[2][2][2] = {};

    __syncthreads();     // Xs visible; last block-wide barrier.

    for (int i = 0; i < 64; i++) {
        if (i + 3 < 64) LOAD_SLICE(i + 3, (i + 3) & 3);
        asm volatile("cp.async.commit_group;");      // real or empty group
        asm volatile("cp.async.wait_group 3;");      // group i is done
        __syncwarp();

        const float2* Bp = Bw + (i & 3) * SLICE_F2 + lane;
        float cR0[4] = {0,0,0,0}, cR1[4] = {0,0,0,0};
        float cI0[4] = {0,0,0,0}, cI1[4] = {0,0,0,0};
#pragma unroll
        for (int k0 = 0; k0 < 8; k0 += 2) {
            float2 bvA = Bp[k0 * 32];
            float2 bvB = Bp[(k0 + 1) * 32];
            unsigned b0 = __float_as_uint(bvA.x), b1 = __float_as_uint(bvA.y);
            unsigned b2 = __float_as_uint(bvB.x), b3 = __float_as_uint(bvB.y);
            MMA_TF32(cR0, aR[k0], b0, b1);
            MMA_TF32(cI0, aI[k0], b0, b1);
            MMA_TF32(cR1, aR[k0 + 1], b2, b3);
            MMA_TF32(cI1, aI[k0 + 1], b2, b3);
        }
#pragma unroll
        for (int rr = 0; rr < 2; rr++) {
            int flocal = g + rr * 8;
#pragma unroll
            for (int b = 0; b < 2; b++) {
                float2 xv = Xs[(b * 64 + i) * 16 + flocal];
#pragma unroll
                for (int cc = 0; cc < 2; cc++) {
                    float kr = cR0[rr * 2 + cc] + cR1[rr * 2 + cc];
                    float ki = cI0[rr * 2 + cc] + cI1[rr * 2 + cc];
                    oR[b][rr][cc] += xv.x * kr - xv.y * ki;
                    oI[b][rr][cc] += xv.x * ki + xv.y * kr;
                }
            }
        }
    }

#pragma unroll
    for (int rr = 0; rr < 2; rr++) {
        int f = f0 + g + rr * 8;
        if (f < NBINS) {
#pragma unroll
            for (int b = 0; b < 2; b++)
#pragma unroll
                for (int cc = 0; cc < 2; cc++) {
                    int o = obase + tg * 2 + cc;
                    d_OutfP[kh][(b * 64 + o) * NBINS + f] =
                        make_float2(oR[b][rr][cc], oI[b][rr][cc]);
                }
        }
    }
}

// ------------------- inverse FFT: sums k-half partials, 2 rows per block ----
__global__ void fft_inv_kernel(float* __restrict__ out) {
    __shared__ float2 buf[NFFT];
    int t0 = 2 * blockIdx.x;
    const float2* P00 = d_OutfP[0] + (size_t)t0 * NBINS;
    const float2* P01 = d_OutfP[1] + (size_t)t0 * NBINS;
    const float2* P10 = d_OutfP[0] + (size_t)(t0 + 1) * NBINS;
    const float2* P11 = d_OutfP[1] + (size_t)(t0 + 1) * NBINS;
    for (int d = threadIdx.x; d < NFFT; d += 512) {
        int src = rev4(d);
        int s = (src <= 2048) ? src : (NFFT - src);
        float2 a = make_float2(P00[s].x + P01[s].x, P00[s].y + P01[s].y);
        float2 b = make_float2(P10[s].x + P11[s].x, P10[s].y + P11[s].y);
        float2 v;
        if (src <= 2048) v = make_float2(a.x - b.y, -a.y - b.x);
        else             v = make_float2(a.x + b.y,  a.y - b.x);
        buf[d] = v;
    }
    fft4_core(buf);
    const float inv = 1.0f / (float)NFFT;
    for (int n = threadIdx.x; n < LL; n += 512) {
        out[t0 * LL + n]       =  buf[n].x * inv;
        out[(t0 + 1) * LL + n] = -buf[n].y * inv;
    }
}

// ============================================================================
extern "C" void kernel_launch(void* const* d_in, const int* in_sizes, int n_in,
                              void* d_out, int out_size) {
    (void)in_sizes; (void)n_in; (void)out_size;
    const float* x  = (const float*)d_in[0];
    const float* W1 = (const float*)d_in[1];
    const float* W2 = (const float*)d_in[2];
    const float* W3 = (const float*)d_in[3];
    float* out = (float*)d_out;

    cudaFuncSetAttribute(k45_kernel,
                         cudaFuncAttributeMaxDynamicSharedMemorySize, K45_SMEM);

    setup_kernel<<<1024, 256>>>(W3);
    gen_h2_kernel<<<2048, 128>>>(W1, W2);
    fft_gx_kernel<<<128, 512>>>(x);
    k45_kernel<<<dim3(129, 2), 256, K45_SMEM>>>();
    fft_inv_kernel<<<64, 512>>>(out);
}